// round 5
// baseline (speedup 1.0000x reference)
#include <cuda_runtime.h>

#define PROBS 256
#define HW 128
#define PLANE (HW*HW)   // 16384 floats = 64KB

// Scratch (device globals: sanctioned workaround for no-alloc rule)
__device__ float g_p[PROBS*PLANE];
__device__ float g_u[2][PROBS*PLANE];
__device__ float g_v[2][PROBS*PLANE];

// ---- constants (double-evaluated, used as float) ----
static constexpr double dDX  = 2.0/9.0;
static constexpr double dDY  = 2.0/127.0;
static constexpr double dDX2 = dDX*dDX;
static constexpr double dDY2 = dDY*dDY;
static constexpr double dDEN = 2.0*(dDX2+dDY2);
static constexpr double dDT = 0.1, dNU = 0.1, dRHO = 1.0, dFRC = 1.0;

#define KA     ((float)(dDY2/dDEN))
#define KB     ((float)(dDX2/dDEN))
#define KC     ((float)(dDX2*dDY2/dDEN))
#define INV2DX ((float)(1.0/(2.0*dDX)))
#define INV2DY ((float)(1.0/(2.0*dDY)))
#define INVDT  ((float)(1.0/dDT))
#define C1     ((float)(dDT/dDX))
#define C2     ((float)(dDT/dDY))
#define C3X    ((float)(dDT/(2.0*dRHO*dDX)))
#define C3Y    ((float)(dDT/(2.0*dRHO*dDY)))
#define C4     ((float)(dNU*dDT/dDX2))
#define C5     ((float)(dNU*dDT/dDY2))
#define FDT    ((float)(dFRC*dDT))

extern __shared__ float dsm[];

// =====================================================================
// Merged prep kernel (unchanged from R3).
// Blocks 0..1023: GEMM p0 = pad(x)@w^T + b_lin.
// Blocks 1024..2047: transpose u0,v0 [b,h,w,d] -> [prob][h][w].
// =====================================================================
__global__ __launch_bounds__(256) void prep_all(const float* __restrict__ x,
                                                const float* __restrict__ u0,
                                                const float* __restrict__ v0,
                                                const float* __restrict__ wm,
                                                const float* __restrict__ bl) {
    int bx = blockIdx.x;
    int tid = threadIdx.x;

    if (bx < 1024) {
        float* xs  = dsm;                // [f][xw] stride 132
        float* wst = dsm + 64*132;       // [f][d]  stride 36
        float* bls = wst + 64*36;        // 32
        int b = bx >> 7;
        int h = bx & 127;
        if (tid < 32) bls[tid] = bl[tid];

        if (h == 0 || h == 127) {
            __syncthreads();
            for (int idx = tid; idx < 4096; idx += 256) {
                int d = idx >> 7, w = idx & 127;
                g_p[(size_t)(b*32+d)*PLANE + h*HW + w] = bls[d];
            }
            return;
        }
        for (int idx = tid; idx < 2048; idx += 256) {
            int d = idx >> 6, f = idx & 63;
            wst[f*36 + d] = wm[idx];
        }
        const float* xrow = x + (size_t)(b*126 + (h-1))*126*64;
        for (int idx = tid; idx < 126*64; idx += 256) {
            int f = idx & 63, xw = idx >> 6;
            xs[f*132 + xw] = xrow[idx];
        }
        __syncthreads();

        int wq = tid & 31;
        int dh = tid >> 5;
        if (wq < 31) {
            unsigned long long acc[8];
            #pragma unroll
            for (int i = 0; i < 8; i++) acc[i] = 0ull;
            #pragma unroll 4
            for (int f = 0; f < 64; f++) {
                ulonglong2 xv = *(const ulonglong2*)&xs[f*132 + 4*wq];
                float4 wv = *(const float4*)&wst[f*36 + 4*dh];
                #pragma unroll
                for (int dd = 0; dd < 4; dd++) {
                    float wf = (dd==0)?wv.x:(dd==1)?wv.y:(dd==2)?wv.z:wv.w;
                    unsigned long long wd;
                    asm("mov.b64 %0,{%1,%1};" : "=l"(wd) : "f"(wf));
                    asm("fma.rn.f32x2 %0,%1,%2,%0;" : "+l"(acc[dd*2  ]) : "l"(xv.x), "l"(wd));
                    asm("fma.rn.f32x2 %0,%1,%2,%0;" : "+l"(acc[dd*2+1]) : "l"(xv.y), "l"(wd));
                }
            }
            #pragma unroll
            for (int dd = 0; dd < 4; dd++) {
                int d = 4*dh + dd;
                float bb = bls[d];
                float* base = g_p + (size_t)(b*32+d)*PLANE + h*HW;
                float a0,a1,a2,a3;
                asm("mov.b64 {%0,%1},%2;" : "=f"(a0), "=f"(a1) : "l"(acc[dd*2]));
                asm("mov.b64 {%0,%1},%2;" : "=f"(a2), "=f"(a3) : "l"(acc[dd*2+1]));
                base[1+4*wq] = a0 + bb;
                base[2+4*wq] = a1 + bb;
                base[3+4*wq] = a2 + bb;
                base[4+4*wq] = a3 + bb;
            }
        } else {
            float acc[4][2] = {};
            #pragma unroll 4
            for (int f = 0; f < 64; f++) {
                float2 xv = *(const float2*)&xs[f*132 + 124];
                float4 wv = *(const float4*)&wst[f*36 + 4*dh];
                float wfv[4] = {wv.x, wv.y, wv.z, wv.w};
                #pragma unroll
                for (int dd = 0; dd < 4; dd++) {
                    acc[dd][0] = fmaf(xv.x, wfv[dd], acc[dd][0]);
                    acc[dd][1] = fmaf(xv.y, wfv[dd], acc[dd][1]);
                }
            }
            #pragma unroll
            for (int dd = 0; dd < 4; dd++) {
                int d = 4*dh + dd;
                float bb = bls[d];
                float* base = g_p + (size_t)(b*32+d)*PLANE + h*HW;
                base[125] = acc[dd][0] + bb;
                base[126] = acc[dd][1] + bb;
                base[0]   = bb;
                base[127] = bb;
            }
        }
    } else {
        float* ts = dsm;   // [w][d] stride 33
        int bb = bx - 1024;
        int b = bb >> 7;
        int h = bb & 127;
        int lane = tid & 31, ww = tid >> 5;
        #pragma unroll
        for (int fld = 0; fld < 2; fld++) {
            const float* src = (fld == 0 ? u0 : v0) + (size_t)(b*HW + h)*HW*32;
            float* dstb = (fld == 0 ? g_u[0] : g_v[0]);
            for (int idx = tid; idx < 4096; idx += 256)
                ts[(idx>>5)*33 + (idx&31)] = src[idx];
            __syncthreads();
            #pragma unroll
            for (int q = 0; q < 4; q++) {
                int d = ww + q*8;
                int w = lane*4;
                float4 v;
                v.x = ts[(w  )*33 + d];
                v.y = ts[(w+1)*33 + d];
                v.z = ts[(w+2)*33 + d];
                v.w = ts[(w+3)*33 + d];
                *(float4*)(dstb + (size_t)(b*32+d)*PLANE + h*HW + w) = v;
            }
            __syncthreads();
        }
    }
}

// =====================================================================
// Sim kernel R4: 128 CTAs x 896 threads. Each CTA runs TWO problems
// (14 warps each, 9 rows/warp, rows 1..126 uniformly). p band in regs;
// mcb and the velocity-phase p-copy time-share one 64KB smem buffer
// per problem (owner-warp-only access -> no extra barriers).
// Named barriers decouple the two problem halves.
// =====================================================================
#define NWP 14        // warps per problem
#define RPW 9         // rows per warp
#define PBUF_F (126*HW)   // 16128 floats per problem

__device__ __forceinline__ void barx(int id) {
    asm volatile("bar.sync %0, 448;" :: "r"(id) : "memory");
}

__global__ __launch_bounds__(896, 1) void sim_kernel(float* __restrict__ out) {
    int tid  = threadIdx.x;
    int lane = tid & 31, wid = tid >> 5;
    int h    = (wid >= NWP) ? 1 : 0;     // which problem half
    int wj   = wid - NWP*h;              // warp index within problem (0..13)
    int prob = 2*blockIdx.x + h;
    const unsigned FULL = 0xffffffffu;
    const int lm = (lane + 31) & 31;
    const int lp = (lane + 1)  & 31;
    const int c0 = lane * 4;
    const int r0 = 1 + wj * RPW;         // rows r0..r0+8
    const int barid = 1 + h;

    float* pb = dsm + h * PBUF_F;                 // p-copy / mcb buffer
    float* hb = dsm + 2 * PBUF_F;                 // halos
    // halo idx: ((h*2+sb)*NWP + w)*2*128 + ns*128 + col
    #define HALO(sb, w, ns) (hb + (((h*2+(sb))*NWP + (w))*2 + (ns))*HW + c0)

    const float* gp = g_p + (size_t)prob * PLANE;
    float* up[2] = {g_u[0] + (size_t)prob*PLANE, g_u[1] + (size_t)prob*PLANE};
    float* vp[2] = {g_v[0] + (size_t)prob*PLANE, g_v[1] + (size_t)prob*PLANE};

    float4 P[RPW];
    float4 hN, hS;

    hN = *(const float4*)(gp + (r0-1)*HW + c0);
    hS = *(const float4*)(gp + (r0+RPW)*HW + c0);

    for (int iter = 0; iter < 3; iter++) {
        const float* U = up[iter & 1];
        const float* V = vp[iter & 1];

        // ---- (1) load P band (iter0: gmem, else: smem p-copy) ----
        if (iter == 0) {
            #pragma unroll
            for (int k = 0; k < RPW; k++)
                P[k] = *(const float4*)(gp + (r0+k)*HW + c0);
        } else {
            #pragma unroll
            for (int k = 0; k < RPW; k++)
                P[k] = *(const float4*)(pb + (r0+k-1)*HW + c0);
        }

        // ---- (2) build mcb = -KC*b into pb (owner rows only) ----
        {
            float4 uN = *(const float4*)(U + (r0-1)*HW + c0);
            float4 uC = *(const float4*)(U + (r0  )*HW + c0);
            float4 vN = *(const float4*)(V + (r0-1)*HW + c0);
            float4 vC = *(const float4*)(V + (r0  )*HW + c0);
            #pragma unroll
            for (int k = 0; k < RPW; k++) {
                int r = r0 + k;
                float4 uS = *(const float4*)(U + (r+1)*HW + c0);
                float4 vS = *(const float4*)(V + (r+1)*HW + c0);
                float uWs = __shfl_sync(FULL, uC.w, lm);
                float uEs = __shfl_sync(FULL, uC.x, lp);
                float vWs = __shfl_sync(FULL, vC.w, lm);
                float vEs = __shfl_sync(FULL, vC.x, lp);
                float uw[4] = {uWs, uC.x, uC.y, uC.z};
                float ue[4] = {uC.y, uC.z, uC.w, uEs};
                float vw[4] = {vWs, vC.x, vC.y, vC.z};
                float ve[4] = {vC.y, vC.z, vC.w, vEs};
                float unv[4] = {uN.x,uN.y,uN.z,uN.w}, usv[4] = {uS.x,uS.y,uS.z,uS.w};
                float vnv[4] = {vN.x,vN.y,vN.z,vN.w}, vsv[4] = {vS.x,vS.y,vS.z,vS.w};
                float o[4];
                #pragma unroll
                for (int q = 0; q < 4; q++) {
                    float dudx = (ue[q] - uw[q]) * INV2DX;
                    float dvdy = (vsv[q] - vnv[q]) * INV2DY;
                    float dudy = (usv[q] - unv[q]) * INV2DY;
                    float dvdx = (ve[q] - vw[q]) * INV2DX;
                    float bt = (dudx + dvdy)*INVDT - dudx*dudx
                             - 2.f*dudy*dvdx - dvdy*dvdy;
                    o[q] = -KC * bt;
                }
                *(float4*)(pb + (r-1)*HW + c0) = make_float4(o[0], o[1], o[2], o[3]);
                uN = uC; uC = uS; vN = vC; vC = vS;
            }
        }

        // ---- (3) 20 Jacobi sweeps ----
        int sb = 0;
        for (int s = 0; s < 20; s++) {
            float4 prev = hN;
            #pragma unroll
            for (int k = 0; k < RPW; k++) {
                float4 cur = P[k];
                float4 nxt = (k < RPW-1) ? P[k+1] : hS;
                float4 m = *(const float4*)(pb + (r0+k-1)*HW + c0);
                float w_ = __shfl_sync(FULL, cur.w, lm);
                float e_ = __shfl_sync(FULL, cur.x, lp);
                float4 o;
                o.x = fmaf(w_   , KA, fmaf(cur.y, KA, fmaf(prev.x, KB, fmaf(nxt.x, KB, m.x))));
                o.y = fmaf(cur.x, KA, fmaf(cur.z, KA, fmaf(prev.y, KB, fmaf(nxt.y, KB, m.y))));
                o.z = fmaf(cur.y, KA, fmaf(cur.w, KA, fmaf(prev.z, KB, fmaf(nxt.z, KB, m.z))));
                o.w = fmaf(cur.z, KA, fmaf(e_   , KA, fmaf(prev.w, KB, fmaf(nxt.w, KB, m.w))));
                prev = cur;
                P[k] = o;
            }
            if (wj == 0)      hN = P[0];        // row0 := row1
            if (wj == NWP-1)  hS = P[RPW-1];    // row127 := row126
            *(float4*)HALO(sb, wj, 0) = P[0];
            *(float4*)HALO(sb, wj, 1) = P[RPW-1];
            barx(barid);
            if (wj > 0)      hN = *(const float4*)HALO(sb, wj-1, 1);
            if (wj < NWP-1)  hS = *(const float4*)HALO(sb, wj+1, 0);
            sb ^= 1;
        }

        // ---- (4) store P band to pb (p-copy; P regs die here) ----
        #pragma unroll
        for (int k = 0; k < RPW; k++)
            *(float4*)(pb + (r0+k-1)*HW + c0) = P[k];

        // ---- (5) velocity step (p read back from pb / halos) ----
        {
            float* Un = up[(iter+1) & 1];
            float* Vn = vp[(iter+1) & 1];
            float4 uN = *(const float4*)(U + (r0-1)*HW + c0);
            float4 uC = *(const float4*)(U + (r0  )*HW + c0);
            float4 vN = *(const float4*)(V + (r0-1)*HW + c0);
            float4 vC = *(const float4*)(V + (r0  )*HW + c0);
            float4 pN = hN;
            float4 pC = *(const float4*)(pb + (r0-1)*HW + c0);
            #pragma unroll
            for (int k = 0; k < RPW; k++) {
                int r = r0 + k;
                float4 uS = *(const float4*)(U + (r+1)*HW + c0);
                float4 vS = *(const float4*)(V + (r+1)*HW + c0);
                float4 pS = (k < RPW-1) ? *(const float4*)(pb + (r0+k)*HW + c0) : hS;
                float uWs = __shfl_sync(FULL, uC.w, lm);
                float uEs = __shfl_sync(FULL, uC.x, lp);
                float vWs = __shfl_sync(FULL, vC.w, lm);
                float vEs = __shfl_sync(FULL, vC.x, lp);
                float pWs = __shfl_sync(FULL, pC.w, lm);
                float pEs = __shfl_sync(FULL, pC.x, lp);
                float uw[4] = {uWs, uC.x, uC.y, uC.z}, ue[4] = {uC.y, uC.z, uC.w, uEs};
                float vw[4] = {vWs, vC.x, vC.y, vC.z}, ve[4] = {vC.y, vC.z, vC.w, vEs};
                float pw[4] = {pWs, pC.x, pC.y, pC.z}, pe[4] = {pC.y, pC.z, pC.w, pEs};
                float ucv[4] = {uC.x,uC.y,uC.z,uC.w}, vcv[4] = {vC.x,vC.y,vC.z,vC.w};
                float unv[4] = {uN.x,uN.y,uN.z,uN.w}, usv[4] = {uS.x,uS.y,uS.z,uS.w};
                float vnv[4] = {vN.x,vN.y,vN.z,vN.w}, vsv[4] = {vS.x,vS.y,vS.z,vS.w};
                float pnv[4] = {pN.x,pN.y,pN.z,pN.w}, psv[4] = {pS.x,pS.y,pS.z,pS.w};
                float uo[4], vo[4];
                #pragma unroll
                for (int q = 0; q < 4; q++) {
                    float uc = ucv[q], vc = vcv[q];
                    uo[q] = uc
                          - C1*uc*(uc - uw[q])
                          - C2*vc*(uc - unv[q])
                          - C3X*(pe[q] - pw[q])
                          + C4*(ue[q] - 2.f*uc + uw[q])
                          + C5*(usv[q] - 2.f*uc + unv[q])
                          + FDT;
                    vo[q] = vc
                          - C1*uc*(vc - vw[q])
                          - C2*vc*(vc - vnv[q])
                          - C3Y*(psv[q] - pnv[q])
                          + C4*(ve[q] - 2.f*vc + vw[q])
                          + C5*(vsv[q] - 2.f*vc + vnv[q]);
                }
                *(float4*)(Un + r*HW + c0) = make_float4(uo[0], uo[1], uo[2], uo[3]);
                *(float4*)(Vn + r*HW + c0) = make_float4(vo[0], vo[1], vo[2], vo[3]);
                uN = uC; uC = uS; vN = vC; vC = vS; pN = pC; pC = pS;
            }
            float4 z = make_float4(0.f, 0.f, 0.f, 0.f);
            if (wj == 0) {
                *(float4*)(Un + c0) = z;
                *(float4*)(Vn + c0) = z;
            }
            if (wj == NWP-1) {
                *(float4*)(Un + 127*HW + c0) = z;
                *(float4*)(Vn + 127*HW + c0) = z;
            }
        }
        barx(barid);   // new u,v visible problem-wide before next build_b
    }

    // output: p[:, -1, :, :] = row 127 = row126 copy = warp13's hS
    if (wj == NWP-1) {
        int b = prob >> 5, d = prob & 31;
        float pv[4] = {hS.x, hS.y, hS.z, hS.w};
        #pragma unroll
        for (int j = 0; j < 4; j++)
            out[(size_t)(b*HW + c0 + j)*32 + d] = pv[j];
    }
}

// =====================================================================
extern "C" void kernel_launch(void* const* d_in, const int* in_sizes, int n_in,
                              void* d_out, int out_size) {
    const float* x  = (const float*)d_in[0];   // (8,126,126,64)
    const float* u0 = (const float*)d_in[1];   // (8,128,128,32)
    const float* v0 = (const float*)d_in[2];   // (8,128,128,32)
    const float* wm = (const float*)d_in[3];   // (32,64)
    const float* bl = (const float*)d_in[4];   // (32,)
    float* out = (float*)d_out;                // (8,128,32)

    int prep_smem = (64*132 + 64*36 + 32) * (int)sizeof(float);   // ~43.2KB
    int sim_smem  = (2*PBUF_F + 2*2*NWP*2*HW) * (int)sizeof(float); // 186368 B

    cudaFuncSetAttribute(sim_kernel, cudaFuncAttributeMaxDynamicSharedMemorySize,
                         sim_smem);

    prep_all<<<2048, 256, prep_smem>>>(x, u0, v0, wm, bl);
    sim_kernel<<<PROBS/2, 896, sim_smem>>>(out);
}

// round 11
// speedup vs baseline: 1.0180x; 1.0180x over previous
#include <cuda_runtime.h>

#define PROBS 256
#define HW 128
#define PLANE (HW*HW)   // 16384 floats = 64KB

// Scratch (device globals: sanctioned workaround for no-alloc rule)
__device__ float g_p[PROBS*PLANE];
__device__ float g_u[2][PROBS*PLANE];
__device__ float g_v[2][PROBS*PLANE];

// ---- constants (double-evaluated, used as float) ----
static constexpr double dDX  = 2.0/9.0;
static constexpr double dDY  = 2.0/127.0;
static constexpr double dDX2 = dDX*dDX;
static constexpr double dDY2 = dDY*dDY;
static constexpr double dDEN = 2.0*(dDX2+dDY2);
static constexpr double dDT = 0.1, dNU = 0.1, dRHO = 1.0, dFRC = 1.0;

#define KA     ((float)(dDY2/dDEN))
#define KB     ((float)(dDX2/dDEN))
#define KC     ((float)(dDX2*dDY2/dDEN))
#define INV2DX ((float)(1.0/(2.0*dDX)))
#define INV2DY ((float)(1.0/(2.0*dDY)))
#define INVDT  ((float)(1.0/dDT))
#define C1     ((float)(dDT/dDX))
#define C2     ((float)(dDT/dDY))
#define C3X    ((float)(dDT/(2.0*dRHO*dDX)))
#define C3Y    ((float)(dDT/(2.0*dRHO*dDY)))
#define C4     ((float)(dNU*dDT/dDX2))
#define C5     ((float)(dNU*dDT/dDY2))
#define FDT    ((float)(dFRC*dDT))

extern __shared__ float dsm[];

// =====================================================================
// Merged prep kernel — verified version (R3/R5).
// Blocks 0..1023: GEMM p0 = pad(x)@w^T + b_lin.
// Blocks 1024..2047: transpose u0,v0 [b,h,w,d] -> [prob][h][w].
// =====================================================================
__global__ __launch_bounds__(256) void prep_all(const float* __restrict__ x,
                                                const float* __restrict__ u0,
                                                const float* __restrict__ v0,
                                                const float* __restrict__ wm,
                                                const float* __restrict__ bl) {
    int bx = blockIdx.x;
    int tid = threadIdx.x;

    if (bx < 1024) {
        float* xs  = dsm;                // [f][xw] stride 132
        float* wst = dsm + 64*132;       // [f][d]  stride 36
        float* bls = wst + 64*36;        // 32
        int b = bx >> 7;
        int h = bx & 127;
        if (tid < 32) bls[tid] = bl[tid];

        if (h == 0 || h == 127) {
            __syncthreads();
            for (int idx = tid; idx < 4096; idx += 256) {
                int d = idx >> 7, w = idx & 127;
                g_p[(size_t)(b*32+d)*PLANE + h*HW + w] = bls[d];
            }
            return;
        }
        for (int idx = tid; idx < 2048; idx += 256) {
            int d = idx >> 6, f = idx & 63;
            wst[f*36 + d] = wm[idx];
        }
        const float* xrow = x + (size_t)(b*126 + (h-1))*126*64;
        for (int idx = tid; idx < 126*64; idx += 256) {
            int f = idx & 63, xw = idx >> 6;
            xs[f*132 + xw] = xrow[idx];
        }
        __syncthreads();

        int wq = tid & 31;
        int dh = tid >> 5;
        if (wq < 31) {
            unsigned long long acc[8];
            #pragma unroll
            for (int i = 0; i < 8; i++) acc[i] = 0ull;
            #pragma unroll 4
            for (int f = 0; f < 64; f++) {
                ulonglong2 xv = *(const ulonglong2*)&xs[f*132 + 4*wq];
                float4 wv = *(const float4*)&wst[f*36 + 4*dh];
                #pragma unroll
                for (int dd = 0; dd < 4; dd++) {
                    float wf = (dd==0)?wv.x:(dd==1)?wv.y:(dd==2)?wv.z:wv.w;
                    unsigned long long wd;
                    asm("mov.b64 %0,{%1,%1};" : "=l"(wd) : "f"(wf));
                    asm("fma.rn.f32x2 %0,%1,%2,%0;" : "+l"(acc[dd*2  ]) : "l"(xv.x), "l"(wd));
                    asm("fma.rn.f32x2 %0,%1,%2,%0;" : "+l"(acc[dd*2+1]) : "l"(xv.y), "l"(wd));
                }
            }
            #pragma unroll
            for (int dd = 0; dd < 4; dd++) {
                int d = 4*dh + dd;
                float bb = bls[d];
                float* base = g_p + (size_t)(b*32+d)*PLANE + h*HW;
                float a0,a1,a2,a3;
                asm("mov.b64 {%0,%1},%2;" : "=f"(a0), "=f"(a1) : "l"(acc[dd*2]));
                asm("mov.b64 {%0,%1},%2;" : "=f"(a2), "=f"(a3) : "l"(acc[dd*2+1]));
                base[1+4*wq] = a0 + bb;
                base[2+4*wq] = a1 + bb;
                base[3+4*wq] = a2 + bb;
                base[4+4*wq] = a3 + bb;
            }
        } else {
            float acc[4][2] = {};
            #pragma unroll 4
            for (int f = 0; f < 64; f++) {
                float2 xv = *(const float2*)&xs[f*132 + 124];
                float4 wv = *(const float4*)&wst[f*36 + 4*dh];
                float wfv[4] = {wv.x, wv.y, wv.z, wv.w};
                #pragma unroll
                for (int dd = 0; dd < 4; dd++) {
                    acc[dd][0] = fmaf(xv.x, wfv[dd], acc[dd][0]);
                    acc[dd][1] = fmaf(xv.y, wfv[dd], acc[dd][1]);
                }
            }
            #pragma unroll
            for (int dd = 0; dd < 4; dd++) {
                int d = 4*dh + dd;
                float bb = bls[d];
                float* base = g_p + (size_t)(b*32+d)*PLANE + h*HW;
                base[125] = acc[dd][0] + bb;
                base[126] = acc[dd][1] + bb;
                base[0]   = bb;
                base[127] = bb;
            }
        }
    } else {
        // ---------------- transpose branch (verified scalar version) ----
        float* ts = dsm;   // [w][d] stride 33
        int bb = bx - 1024;
        int b = bb >> 7;
        int h = bb & 127;
        int lane = tid & 31, ww = tid >> 5;
        #pragma unroll
        for (int fld = 0; fld < 2; fld++) {
            const float* src = (fld == 0 ? u0 : v0) + (size_t)(b*HW + h)*HW*32;
            float* dstb = (fld == 0 ? g_u[0] : g_v[0]);
            for (int idx = tid; idx < 4096; idx += 256)
                ts[(idx>>5)*33 + (idx&31)] = src[idx];
            __syncthreads();
            #pragma unroll
            for (int q = 0; q < 4; q++) {
                int d = ww + q*8;
                int w = lane*4;
                float4 v;
                v.x = ts[(w  )*33 + d];
                v.y = ts[(w+1)*33 + d];
                v.z = ts[(w+2)*33 + d];
                v.w = ts[(w+3)*33 + d];
                *(float4*)(dstb + (size_t)(b*32+d)*PLANE + h*HW + w) = v;
            }
            __syncthreads();
        }
    }
}

// =====================================================================
// Sim kernel R11: 256 CTAs x 640 threads (20 warps), ONE problem/CTA.
// Warps 0..5: 7 rows, warps 6..19: 6 rows (126 interior rows total).
// P and mcb both fp32 REGISTER-resident for all 3 iterations (the fp16
// mcb of R6/R8/R10 overflowed: the scheme is divergent, mcb ~ 1e11 by
// iter 3). smem = 40KB halo ring only. u,v double-buffered in gmem.
// =====================================================================
#define NWP 20
#define KMAX 7

__global__ __launch_bounds__(640, 1) void sim_kernel(float* __restrict__ out) {
    __shared__ float halo[2][NWP][2][HW];   // 40960 B

    int tid  = threadIdx.x;
    int lane = tid & 31, wj = tid >> 5;
    int prob = blockIdx.x;
    const unsigned FULL = 0xffffffffu;
    const int lm = (lane + 31) & 31;
    const int lp = (lane + 1)  & 31;
    const int c0 = lane * 4;
    const int kLast = (wj < 6) ? 6 : 5;
    const int r0 = (wj < 6) ? (1 + wj*7) : (43 + (wj-6)*6);

    const float* gp = g_p + (size_t)prob * PLANE;
    float* up[2] = {g_u[0] + (size_t)prob*PLANE, g_u[1] + (size_t)prob*PLANE};
    float* vp[2] = {g_v[0] + (size_t)prob*PLANE, g_v[1] + (size_t)prob*PLANE};

    float4 P[KMAX];
    float4 mcb[KMAX];     // -KC*b, fp32, register-resident
    float4 hN, hS;

    #pragma unroll
    for (int k = 0; k < KMAX; k++)
        if (k <= kLast) P[k] = *(const float4*)(gp + (r0+k)*HW + c0);
    hN = *(const float4*)(gp + (r0-1      )*HW + c0);
    hS = *(const float4*)(gp + (r0+kLast+1)*HW + c0);

    for (int iter = 0; iter < 3; iter++) {
        const float* U = up[iter & 1];
        const float* V = vp[iter & 1];

        // ---- (b) build mcb = -KC*b (registers only) ----
        {
            float4 uN = *(const float4*)(U + (r0-1)*HW + c0);
            float4 uC = *(const float4*)(U + (r0  )*HW + c0);
            float4 vN = *(const float4*)(V + (r0-1)*HW + c0);
            float4 vC = *(const float4*)(V + (r0  )*HW + c0);
            #pragma unroll
            for (int k = 0; k < KMAX; k++) {
                if (k <= kLast) {
                    int r = r0 + k;
                    float4 uS = *(const float4*)(U + (r+1)*HW + c0);
                    float4 vS = *(const float4*)(V + (r+1)*HW + c0);
                    float uWs = __shfl_sync(FULL, uC.w, lm);
                    float uEs = __shfl_sync(FULL, uC.x, lp);
                    float vWs = __shfl_sync(FULL, vC.w, lm);
                    float vEs = __shfl_sync(FULL, vC.x, lp);
                    float uw[4] = {uWs, uC.x, uC.y, uC.z};
                    float ue[4] = {uC.y, uC.z, uC.w, uEs};
                    float vw[4] = {vWs, vC.x, vC.y, vC.z};
                    float ve[4] = {vC.y, vC.z, vC.w, vEs};
                    float unv[4] = {uN.x,uN.y,uN.z,uN.w}, usv[4] = {uS.x,uS.y,uS.z,uS.w};
                    float vnv[4] = {vN.x,vN.y,vN.z,vN.w}, vsv[4] = {vS.x,vS.y,vS.z,vS.w};
                    float o[4];
                    #pragma unroll
                    for (int q = 0; q < 4; q++) {
                        float dudx = (ue[q] - uw[q]) * INV2DX;
                        float dvdy = (vsv[q] - vnv[q]) * INV2DY;
                        float dudy = (usv[q] - unv[q]) * INV2DY;
                        float dvdx = (ve[q] - vw[q]) * INV2DX;
                        float bt = (dudx + dvdy)*INVDT - dudx*dudx
                                 - 2.f*dudy*dvdx - dvdy*dvdy;
                        o[q] = -KC * bt;
                    }
                    mcb[k] = make_float4(o[0], o[1], o[2], o[3]);
                    uN = uC; uC = uS; vN = vC; vC = vS;
                }
            }
        }

        // ---- (c) 20 Jacobi sweeps ----
        int sb = 0;
        for (int s = 0; s < 20; s++) {
            float4 prev = hN;
            #pragma unroll
            for (int k = 0; k < KMAX; k++) {
                if (k <= kLast) {
                    float4 cur = P[k];
                    float4 nxt;
                    if (k == KMAX-1) nxt = hS;
                    else             nxt = (k == kLast) ? hS : P[k+1];
                    float w_ = __shfl_sync(FULL, cur.w, lm);
                    float e_ = __shfl_sync(FULL, cur.x, lp);
                    float4 o;
                    o.x = fmaf(w_   , KA, fmaf(cur.y, KA, fmaf(prev.x, KB, fmaf(nxt.x, KB, mcb[k].x))));
                    o.y = fmaf(cur.x, KA, fmaf(cur.z, KA, fmaf(prev.y, KB, fmaf(nxt.y, KB, mcb[k].y))));
                    o.z = fmaf(cur.y, KA, fmaf(cur.w, KA, fmaf(prev.z, KB, fmaf(nxt.z, KB, mcb[k].z))));
                    o.w = fmaf(cur.z, KA, fmaf(e_   , KA, fmaf(prev.w, KB, fmaf(nxt.w, KB, mcb[k].w))));
                    prev = cur;
                    P[k] = o;
                }
            }
            if (wj == 0)      hN = P[0];        // p row0 := row1
            if (wj == NWP-1)  hS = P[kLast];    // p row127 := row126
            *(float4*)&halo[sb][wj][0][c0] = P[0];
            *(float4*)&halo[sb][wj][1][c0] = P[kLast];
            __syncthreads();
            if (wj > 0)      hN = *(const float4*)&halo[sb][wj-1][1][c0];
            if (wj < NWP-1)  hS = *(const float4*)&halo[sb][wj+1][0][c0];
            sb ^= 1;
        }

        // ---- (d) velocity step: old buffers -> new buffers; p from registers ----
        {
            float* Un = up[(iter+1) & 1];
            float* Vn = vp[(iter+1) & 1];
            float4 uN = *(const float4*)(U + (r0-1)*HW + c0);
            float4 uC = *(const float4*)(U + (r0  )*HW + c0);
            float4 vN = *(const float4*)(V + (r0-1)*HW + c0);
            float4 vC = *(const float4*)(V + (r0  )*HW + c0);
            #pragma unroll
            for (int k = 0; k < KMAX; k++) {
                if (k <= kLast) {
                    int r = r0 + k;
                    float4 uS = *(const float4*)(U + (r+1)*HW + c0);
                    float4 vS = *(const float4*)(V + (r+1)*HW + c0);
                    float4 pN = (k == 0) ? hN : P[k-1];
                    float4 pC = P[k];
                    float4 pS;
                    if (k == KMAX-1) pS = hS;
                    else             pS = (k == kLast) ? hS : P[k+1];
                    float uWs = __shfl_sync(FULL, uC.w, lm);
                    float uEs = __shfl_sync(FULL, uC.x, lp);
                    float vWs = __shfl_sync(FULL, vC.w, lm);
                    float vEs = __shfl_sync(FULL, vC.x, lp);
                    float pWs = __shfl_sync(FULL, pC.w, lm);
                    float pEs = __shfl_sync(FULL, pC.x, lp);
                    float uw[4] = {uWs, uC.x, uC.y, uC.z}, ue[4] = {uC.y, uC.z, uC.w, uEs};
                    float vw[4] = {vWs, vC.x, vC.y, vC.z}, ve[4] = {vC.y, vC.z, vC.w, vEs};
                    float pw[4] = {pWs, pC.x, pC.y, pC.z}, pe[4] = {pC.y, pC.z, pC.w, pEs};
                    float ucv[4] = {uC.x,uC.y,uC.z,uC.w}, vcv[4] = {vC.x,vC.y,vC.z,vC.w};
                    float unv[4] = {uN.x,uN.y,uN.z,uN.w}, usv[4] = {uS.x,uS.y,uS.z,uS.w};
                    float vnv[4] = {vN.x,vN.y,vN.z,vN.w}, vsv[4] = {vS.x,vS.y,vS.z,vS.w};
                    float pnv[4] = {pN.x,pN.y,pN.z,pN.w}, psv[4] = {pS.x,pS.y,pS.z,pS.w};
                    float uo[4], vo[4];
                    #pragma unroll
                    for (int q = 0; q < 4; q++) {
                        float uc = ucv[q], vc = vcv[q];
                        uo[q] = uc
                              - C1*uc*(uc - uw[q])
                              - C2*vc*(uc - unv[q])
                              - C3X*(pe[q] - pw[q])
                              + C4*(ue[q] - 2.f*uc + uw[q])
                              + C5*(usv[q] - 2.f*uc + unv[q])
                              + FDT;
                        vo[q] = vc
                              - C1*uc*(vc - vw[q])
                              - C2*vc*(vc - vnv[q])
                              - C3Y*(psv[q] - pnv[q])
                              + C4*(ve[q] - 2.f*vc + vw[q])
                              + C5*(vsv[q] - 2.f*vc + vnv[q]);
                    }
                    *(float4*)(Un + r*HW + c0) = make_float4(uo[0], uo[1], uo[2], uo[3]);
                    *(float4*)(Vn + r*HW + c0) = make_float4(vo[0], vo[1], vo[2], vo[3]);
                    uN = uC; uC = uS; vN = vC; vC = vS;
                }
            }
            float4 z = make_float4(0.f, 0.f, 0.f, 0.f);
            if (wj == 0) {
                *(float4*)(Un + c0) = z;
                *(float4*)(Vn + c0) = z;
            }
            if (wj == NWP-1) {
                *(float4*)(Un + 127*HW + c0) = z;
                *(float4*)(Vn + 127*HW + c0) = z;
            }
        }
        __syncthreads();   // new u,v visible CTA-wide before next build_b
    }

    // output: p[:, -1, :, :] = row 127 (= row126 copy) = warp19's hS
    if (wj == NWP-1) {
        int b = prob >> 5, d = prob & 31;
        float pv[4] = {hS.x, hS.y, hS.z, hS.w};
        #pragma unroll
        for (int j = 0; j < 4; j++)
            out[(size_t)(b*HW + c0 + j)*32 + d] = pv[j];
    }
}

// =====================================================================
extern "C" void kernel_launch(void* const* d_in, const int* in_sizes, int n_in,
                              void* d_out, int out_size) {
    const float* x  = (const float*)d_in[0];   // (8,126,126,64)
    const float* u0 = (const float*)d_in[1];   // (8,128,128,32)
    const float* v0 = (const float*)d_in[2];   // (8,128,128,32)
    const float* wm = (const float*)d_in[3];   // (32,64)
    const float* bl = (const float*)d_in[4];   // (32,)
    float* out = (float*)d_out;                // (8,128,32)

    int prep_smem = (64*132 + 64*36 + 32) * (int)sizeof(float);

    prep_all<<<2048, 256, prep_smem>>>(x, u0, v0, wm, bl);
    sim_kernel<<<PROBS, 640>>>(out);
}

// round 14
// speedup vs baseline: 1.2573x; 1.2350x over previous
#include <cuda_runtime.h>

#define PROBS 256
#define HW 128
#define PLANE (HW*HW)   // 16384 floats = 64KB

// Scratch (device globals: sanctioned workaround for no-alloc rule)
__device__ float g_p[PROBS*PLANE];
__device__ float g_u[2][PROBS*PLANE];
__device__ float g_v[2][PROBS*PLANE];

// ---- constants (double-evaluated, used as float) ----
static constexpr double dDX  = 2.0/9.0;
static constexpr double dDY  = 2.0/127.0;
static constexpr double dDX2 = dDX*dDX;
static constexpr double dDY2 = dDY*dDY;
static constexpr double dDEN = 2.0*(dDX2+dDY2);
static constexpr double dDT = 0.1, dNU = 0.1, dRHO = 1.0, dFRC = 1.0;

#define KA     ((float)(dDY2/dDEN))
#define KB     ((float)(dDX2/dDEN))
#define KC     ((float)(dDX2*dDY2/dDEN))
#define INV2DX ((float)(1.0/(2.0*dDX)))
#define INV2DY ((float)(1.0/(2.0*dDY)))
#define INVDT  ((float)(1.0/dDT))
#define C1     ((float)(dDT/dDX))
#define C2     ((float)(dDT/dDY))
#define C3X    ((float)(dDT/(2.0*dRHO*dDX)))
#define C3Y    ((float)(dDT/(2.0*dRHO*dDY)))
#define C4     ((float)(dNU*dDT/dDX2))
#define C5     ((float)(dNU*dDT/dDY2))
#define FDT    ((float)(dFRC*dDT))

extern __shared__ float dsm[];

// =====================================================================
// Merged prep kernel — verified version (unchanged).
// Blocks 0..1023: GEMM p0 = pad(x)@w^T + b_lin.
// Blocks 1024..2047: transpose u0,v0 [b,h,w,d] -> [prob][h][w].
// =====================================================================
__global__ __launch_bounds__(256) void prep_all(const float* __restrict__ x,
                                                const float* __restrict__ u0,
                                                const float* __restrict__ v0,
                                                const float* __restrict__ wm,
                                                const float* __restrict__ bl) {
    int bx = blockIdx.x;
    int tid = threadIdx.x;

    if (bx < 1024) {
        float* xs  = dsm;                // [f][xw] stride 132
        float* wst = dsm + 64*132;       // [f][d]  stride 36
        float* bls = wst + 64*36;        // 32
        int b = bx >> 7;
        int h = bx & 127;
        if (tid < 32) bls[tid] = bl[tid];

        if (h == 0 || h == 127) {
            __syncthreads();
            for (int idx = tid; idx < 4096; idx += 256) {
                int d = idx >> 7, w = idx & 127;
                g_p[(size_t)(b*32+d)*PLANE + h*HW + w] = bls[d];
            }
            return;
        }
        for (int idx = tid; idx < 2048; idx += 256) {
            int d = idx >> 6, f = idx & 63;
            wst[f*36 + d] = wm[idx];
        }
        const float* xrow = x + (size_t)(b*126 + (h-1))*126*64;
        for (int idx = tid; idx < 126*64; idx += 256) {
            int f = idx & 63, xw = idx >> 6;
            xs[f*132 + xw] = xrow[idx];
        }
        __syncthreads();

        int wq = tid & 31;
        int dh = tid >> 5;
        if (wq < 31) {
            unsigned long long acc[8];
            #pragma unroll
            for (int i = 0; i < 8; i++) acc[i] = 0ull;
            #pragma unroll 4
            for (int f = 0; f < 64; f++) {
                ulonglong2 xv = *(const ulonglong2*)&xs[f*132 + 4*wq];
                float4 wv = *(const float4*)&wst[f*36 + 4*dh];
                #pragma unroll
                for (int dd = 0; dd < 4; dd++) {
                    float wf = (dd==0)?wv.x:(dd==1)?wv.y:(dd==2)?wv.z:wv.w;
                    unsigned long long wd;
                    asm("mov.b64 %0,{%1,%1};" : "=l"(wd) : "f"(wf));
                    asm("fma.rn.f32x2 %0,%1,%2,%0;" : "+l"(acc[dd*2  ]) : "l"(xv.x), "l"(wd));
                    asm("fma.rn.f32x2 %0,%1,%2,%0;" : "+l"(acc[dd*2+1]) : "l"(xv.y), "l"(wd));
                }
            }
            #pragma unroll
            for (int dd = 0; dd < 4; dd++) {
                int d = 4*dh + dd;
                float bb = bls[d];
                float* base = g_p + (size_t)(b*32+d)*PLANE + h*HW;
                float a0,a1,a2,a3;
                asm("mov.b64 {%0,%1},%2;" : "=f"(a0), "=f"(a1) : "l"(acc[dd*2]));
                asm("mov.b64 {%0,%1},%2;" : "=f"(a2), "=f"(a3) : "l"(acc[dd*2+1]));
                base[1+4*wq] = a0 + bb;
                base[2+4*wq] = a1 + bb;
                base[3+4*wq] = a2 + bb;
                base[4+4*wq] = a3 + bb;
            }
        } else {
            float acc[4][2] = {};
            #pragma unroll 4
            for (int f = 0; f < 64; f++) {
                float2 xv = *(const float2*)&xs[f*132 + 124];
                float4 wv = *(const float4*)&wst[f*36 + 4*dh];
                float wfv[4] = {wv.x, wv.y, wv.z, wv.w};
                #pragma unroll
                for (int dd = 0; dd < 4; dd++) {
                    acc[dd][0] = fmaf(xv.x, wfv[dd], acc[dd][0]);
                    acc[dd][1] = fmaf(xv.y, wfv[dd], acc[dd][1]);
                }
            }
            #pragma unroll
            for (int dd = 0; dd < 4; dd++) {
                int d = 4*dh + dd;
                float bb = bls[d];
                float* base = g_p + (size_t)(b*32+d)*PLANE + h*HW;
                base[125] = acc[dd][0] + bb;
                base[126] = acc[dd][1] + bb;
                base[0]   = bb;
                base[127] = bb;
            }
        }
    } else {
        // ---------------- transpose branch (verified) ----------------
        float* ts = dsm;   // [w][d] stride 33
        int bb = bx - 1024;
        int b = bb >> 7;
        int h = bb & 127;
        int lane = tid & 31, ww = tid >> 5;
        #pragma unroll
        for (int fld = 0; fld < 2; fld++) {
            const float* src = (fld == 0 ? u0 : v0) + (size_t)(b*HW + h)*HW*32;
            float* dstb = (fld == 0 ? g_u[0] : g_v[0]);
            for (int idx = tid; idx < 4096; idx += 256)
                ts[(idx>>5)*33 + (idx&31)] = src[idx];
            __syncthreads();
            #pragma unroll
            for (int q = 0; q < 4; q++) {
                int d = ww + q*8;
                int w = lane*4;
                float4 v;
                v.x = ts[(w  )*33 + d];
                v.y = ts[(w+1)*33 + d];
                v.z = ts[(w+2)*33 + d];
                v.w = ts[(w+3)*33 + d];
                *(float4*)(dstb + (size_t)(b*32+d)*PLANE + h*HW + w) = v;
            }
            __syncthreads();
        }
    }
}

// =====================================================================
// Sim kernel R12: 256 CTAs x 576 threads (18 warps), ONE problem/CTA,
// UNIFORM 7 rows per warp (18*7 = 126). P + fp32 mcb register-resident.
// Sweep shfls are pre-batched (14 issues back-to-back) so the 26-cyc
// SHFL latency is covered by the issue stream instead of stalling the
// post-barrier lockstepped FFMA chain.
// =====================================================================
#define NWP 18
#define RPW 7

__global__ __launch_bounds__(576, 1) void sim_kernel(float* __restrict__ out) {
    __shared__ float halo[2][NWP][2][HW];   // 36864 B

    int tid  = threadIdx.x;
    int lane = tid & 31, wj = tid >> 5;
    int prob = blockIdx.x;
    const unsigned FULL = 0xffffffffu;
    const int lm = (lane + 31) & 31;
    const int lp = (lane + 1)  & 31;
    const int c0 = lane * 4;
    const int r0 = 1 + wj * RPW;           // rows r0..r0+6

    const float* gp = g_p + (size_t)prob * PLANE;
    float* up[2] = {g_u[0] + (size_t)prob*PLANE, g_u[1] + (size_t)prob*PLANE};
    float* vp[2] = {g_v[0] + (size_t)prob*PLANE, g_v[1] + (size_t)prob*PLANE};

    float4 P[RPW];
    float4 mcb[RPW];     // -KC*b, fp32, register-resident
    float4 hN, hS;

    #pragma unroll
    for (int k = 0; k < RPW; k++)
        P[k] = *(const float4*)(gp + (r0+k)*HW + c0);
    hN = *(const float4*)(gp + (r0-1  )*HW + c0);
    hS = *(const float4*)(gp + (r0+RPW)*HW + c0);

    for (int iter = 0; iter < 3; iter++) {
        const float* U = up[iter & 1];
        const float* V = vp[iter & 1];

        // ---- (b) build mcb = -KC*b (registers only) ----
        {
            float4 uN = *(const float4*)(U + (r0-1)*HW + c0);
            float4 uC = *(const float4*)(U + (r0  )*HW + c0);
            float4 vN = *(const float4*)(V + (r0-1)*HW + c0);
            float4 vC = *(const float4*)(V + (r0  )*HW + c0);
            #pragma unroll
            for (int k = 0; k < RPW; k++) {
                int r = r0 + k;
                float4 uS = *(const float4*)(U + (r+1)*HW + c0);
                float4 vS = *(const float4*)(V + (r+1)*HW + c0);
                float uWs = __shfl_sync(FULL, uC.w, lm);
                float uEs = __shfl_sync(FULL, uC.x, lp);
                float vWs = __shfl_sync(FULL, vC.w, lm);
                float vEs = __shfl_sync(FULL, vC.x, lp);
                float uw[4] = {uWs, uC.x, uC.y, uC.z};
                float ue[4] = {uC.y, uC.z, uC.w, uEs};
                float vw[4] = {vWs, vC.x, vC.y, vC.z};
                float ve[4] = {vC.y, vC.z, vC.w, vEs};
                float unv[4] = {uN.x,uN.y,uN.z,uN.w}, usv[4] = {uS.x,uS.y,uS.z,uS.w};
                float vnv[4] = {vN.x,vN.y,vN.z,vN.w}, vsv[4] = {vS.x,vS.y,vS.z,vS.w};
                float o[4];
                #pragma unroll
                for (int q = 0; q < 4; q++) {
                    float dudx = (ue[q] - uw[q]) * INV2DX;
                    float dvdy = (vsv[q] - vnv[q]) * INV2DY;
                    float dudy = (usv[q] - unv[q]) * INV2DY;
                    float dvdx = (ve[q] - vw[q]) * INV2DX;
                    float bt = (dudx + dvdy)*INVDT - dudx*dudx
                             - 2.f*dudy*dvdx - dvdy*dvdy;
                    o[q] = -KC * bt;
                }
                mcb[k] = make_float4(o[0], o[1], o[2], o[3]);
                uN = uC; uC = uS; vN = vC; vC = vS;
            }
        }

        // ---- (c) 20 Jacobi sweeps, shfls pre-batched ----
        int sb = 0;
        for (int s = 0; s < 20; s++) {
            // batch all E/W shuffles first: they read PRE-sweep P values,
            // 14 back-to-back issues cover the shfl latency.
            float wv[RPW], ev[RPW];
            #pragma unroll
            for (int k = 0; k < RPW; k++) {
                wv[k] = __shfl_sync(FULL, P[k].w, lm);
                ev[k] = __shfl_sync(FULL, P[k].x, lp);
            }
            float4 prev = hN;
            #pragma unroll
            for (int k = 0; k < RPW; k++) {
                float4 cur = P[k];
                float4 nxt = (k < RPW-1) ? P[k+1] : hS;
                float4 o;
                o.x = fmaf(wv[k], KA, fmaf(cur.y, KA, fmaf(prev.x, KB, fmaf(nxt.x, KB, mcb[k].x))));
                o.y = fmaf(cur.x, KA, fmaf(cur.z, KA, fmaf(prev.y, KB, fmaf(nxt.y, KB, mcb[k].y))));
                o.z = fmaf(cur.y, KA, fmaf(cur.w, KA, fmaf(prev.z, KB, fmaf(nxt.z, KB, mcb[k].z))));
                o.w = fmaf(cur.z, KA, fmaf(ev[k], KA, fmaf(prev.w, KB, fmaf(nxt.w, KB, mcb[k].w))));
                prev = cur;
                P[k] = o;
            }
            if (wj == 0)      hN = P[0];        // p row0 := row1
            if (wj == NWP-1)  hS = P[RPW-1];    // p row127 := row126
            *(float4*)&halo[sb][wj][0][c0] = P[0];
            *(float4*)&halo[sb][wj][1][c0] = P[RPW-1];
            __syncthreads();
            if (wj > 0)      hN = *(const float4*)&halo[sb][wj-1][1][c0];
            if (wj < NWP-1)  hS = *(const float4*)&halo[sb][wj+1][0][c0];
            sb ^= 1;
        }

        // ---- (d) velocity step: old buffers -> new buffers; p from regs ----
        {
            float* Un = up[(iter+1) & 1];
            float* Vn = vp[(iter+1) & 1];
            float4 uN = *(const float4*)(U + (r0-1)*HW + c0);
            float4 uC = *(const float4*)(U + (r0  )*HW + c0);
            float4 vN = *(const float4*)(V + (r0-1)*HW + c0);
            float4 vC = *(const float4*)(V + (r0  )*HW + c0);
            #pragma unroll
            for (int k = 0; k < RPW; k++) {
                int r = r0 + k;
                float4 uS = *(const float4*)(U + (r+1)*HW + c0);
                float4 vS = *(const float4*)(V + (r+1)*HW + c0);
                float4 pN = (k == 0)     ? hN : P[k-1];
                float4 pC = P[k];
                float4 pS = (k == RPW-1) ? hS : P[k+1];
                float uWs = __shfl_sync(FULL, uC.w, lm);
                float uEs = __shfl_sync(FULL, uC.x, lp);
                float vWs = __shfl_sync(FULL, vC.w, lm);
                float vEs = __shfl_sync(FULL, vC.x, lp);
                float pWs = __shfl_sync(FULL, pC.w, lm);
                float pEs = __shfl_sync(FULL, pC.x, lp);
                float uw[4] = {uWs, uC.x, uC.y, uC.z}, ue[4] = {uC.y, uC.z, uC.w, uEs};
                float vw[4] = {vWs, vC.x, vC.y, vC.z}, ve[4] = {vC.y, vC.z, vC.w, vEs};
                float pw[4] = {pWs, pC.x, pC.y, pC.z}, pe[4] = {pC.y, pC.z, pC.w, pEs};
                float ucv[4] = {uC.x,uC.y,uC.z,uC.w}, vcv[4] = {vC.x,vC.y,vC.z,vC.w};
                float unv[4] = {uN.x,uN.y,uN.z,uN.w}, usv[4] = {uS.x,uS.y,uS.z,uS.w};
                float vnv[4] = {vN.x,vN.y,vN.z,vN.w}, vsv[4] = {vS.x,vS.y,vS.z,vS.w};
                float pnv[4] = {pN.x,pN.y,pN.z,pN.w}, psv[4] = {pS.x,pS.y,pS.z,pS.w};
                float uo[4], vo[4];
                #pragma unroll
                for (int q = 0; q < 4; q++) {
                    float uc = ucv[q], vc = vcv[q];
                    uo[q] = uc
                          - C1*uc*(uc - uw[q])
                          - C2*vc*(uc - unv[q])
                          - C3X*(pe[q] - pw[q])
                          + C4*(ue[q] - 2.f*uc + uw[q])
                          + C5*(usv[q] - 2.f*uc + unv[q])
                          + FDT;
                    vo[q] = vc
                          - C1*uc*(vc - vw[q])
                          - C2*vc*(vc - vnv[q])
                          - C3Y*(psv[q] - pnv[q])
                          + C4*(ve[q] - 2.f*vc + vw[q])
                          + C5*(vsv[q] - 2.f*vc + vnv[q]);
                }
                *(float4*)(Un + r*HW + c0) = make_float4(uo[0], uo[1], uo[2], uo[3]);
                *(float4*)(Vn + r*HW + c0) = make_float4(vo[0], vo[1], vo[2], vo[3]);
                uN = uC; uC = uS; vN = vC; vC = vS;
            }
            float4 z = make_float4(0.f, 0.f, 0.f, 0.f);
            if (wj == 0) {
                *(float4*)(Un + c0) = z;
                *(float4*)(Vn + c0) = z;
            }
            if (wj == NWP-1) {
                *(float4*)(Un + 127*HW + c0) = z;
                *(float4*)(Vn + 127*HW + c0) = z;
            }
        }
        __syncthreads();   // new u,v visible CTA-wide before next build_b
    }

    // output: p[:, -1, :, :] = row 127 (= row126 copy) = warp17's hS
    if (wj == NWP-1) {
        int b = prob >> 5, d = prob & 31;
        float pv[4] = {hS.x, hS.y, hS.z, hS.w};
        #pragma unroll
        for (int j = 0; j < 4; j++)
            out[(size_t)(b*HW + c0 + j)*32 + d] = pv[j];
    }
}

// =====================================================================
extern "C" void kernel_launch(void* const* d_in, const int* in_sizes, int n_in,
                              void* d_out, int out_size) {
    const float* x  = (const float*)d_in[0];   // (8,126,126,64)
    const float* u0 = (const float*)d_in[1];   // (8,128,128,32)
    const float* v0 = (const float*)d_in[2];   // (8,128,128,32)
    const float* wm = (const float*)d_in[3];   // (32,64)
    const float* bl = (const float*)d_in[4];   // (32,)
    float* out = (float*)d_out;                // (8,128,32)

    int prep_smem = (64*132 + 64*36 + 32) * (int)sizeof(float);

    prep_all<<<2048, 256, prep_smem>>>(x, u0, v0, wm, bl);
    sim_kernel<<<PROBS, 576>>>(out);
}